// round 3
// baseline (speedup 1.0000x reference)
#include <cuda_runtime.h>
#include <cuda_bf16.h>
#include <math.h>

#define BATCH  64
#define NPTS   128
#define FEAT   4
#define HID    100
#define NPAIRS 8128   // C(128,2)

// Precomputed per-point projections, k-major:
//   g_A[b][k][i] = d[k] + sum_f x[b][i][f] * M[f][k]       (i-part, bias folded)
//   g_C[b][k][j] =        sum_f x[b][j][f] * M[4+f][k]     (j-part)
// where M[f][k] = sum_t W1[f][t]*W2[t][k],  d[k] = b2[k] + sum_t b1[t]*W2[t][k]
__device__ __align__(16) float g_A[BATCH * HID * NPTS];   // 3.125 MB
__device__ __align__(16) float g_C[BATCH * HID * NPTS];

// 16x16 tile list over the 8x8 upper triangle (jt >= it): 36 tiles
__constant__ unsigned char TCI[36] = {0,0,0,0,0,0,0,0, 1,1,1,1,1,1,1, 2,2,2,2,2,2,
                                      3,3,3,3,3, 4,4,4,4, 5,5,5, 6,6, 7};
__constant__ unsigned char TCJ[36] = {0,1,2,3,4,5,6,7, 1,2,3,4,5,6,7, 2,3,4,5,6,7,
                                      3,4,5,6,7, 4,5,6,7, 5,6,7, 6,7, 7};

// ---------------------------------------------------------------------------
// Kernel 1: fused fold + per-point projection. One CTA per batch (64 CTAs,
// 256 threads). Each CTA redundantly folds W1@W2 in smem (90 KFLOP — noise),
// which removes the serial fold kernel and hides the cold-DRAM latency of
// W1/W2 behind 64 concurrent CTAs (L2 dedups the shared lines).
// ---------------------------------------------------------------------------
__global__ __launch_bounds__(256)
void precomp_kernel(const float* __restrict__ x,    // [64,128,4]
                    const float* __restrict__ W1,   // [8,100]
                    const float* __restrict__ b1,   // [100]
                    const float* __restrict__ W2,   // [100,100]
                    const float* __restrict__ b2)   // [100]
{
    __shared__ __align__(16) float W2s[HID * HID];   // 40 KB
    __shared__ __align__(16) float W1s[8 * HID];
    __shared__ float b1s[HID];
    __shared__ float Ms[8 * HID];
    __shared__ float ds[HID];
    __shared__ float4 xs[NPTS];

    const int tid = threadIdx.x;
    const int b   = blockIdx.x;

    // --- stage weights + x into smem (vectorized, coalesced) ---
    for (int q = tid; q < (HID * HID) / 4; q += 256)          // 2500 float4
        reinterpret_cast<float4*>(W2s)[q] = reinterpret_cast<const float4*>(W2)[q];
    for (int q = tid; q < (8 * HID) / 4; q += 256)            // 200 float4
        reinterpret_cast<float4*>(W1s)[q] = reinterpret_cast<const float4*>(W1)[q];
    if (tid < HID) b1s[tid] = b1[tid];
    if (tid >= 128 && tid < 128 + NPTS)
        xs[tid - 128] = reinterpret_cast<const float4*>(x)[b * NPTS + (tid - 128)];
    __syncthreads();

    // --- fold: Ms[f][k] = sum_t W1s[f][t] * W2s[t][k] ---
    for (int e = tid; e < 8 * HID; e += 256) {
        int f = e / HID;
        int k = e - f * HID;
        float acc = 0.f;
        #pragma unroll 4
        for (int t = 0; t < HID; t++)
            acc = fmaf(W1s[f * HID + t], W2s[t * HID + k], acc);
        Ms[e] = acc;
    }
    // --- ds[k] = b2[k] + sum_t b1[t] * W2s[t][k] ---
    if (tid < HID) {
        int k = tid;
        float acc = 0.f;
        #pragma unroll 4
        for (int t = 0; t < HID; t++)
            acc = fmaf(b1s[t], W2s[t * HID + k], acc);
        ds[k] = acc + b2[k];
    }
    __syncthreads();

    // --- project: A/C for this batch, k-major, coalesced stores ---
    float* Ab = g_A + (size_t)b * (HID * NPTS);
    float* Cb = g_C + (size_t)b * (HID * NPTS);

    for (int e = tid; e < HID * NPTS; e += 256) {
        int i = e & (NPTS - 1);
        int k = e >> 7;
        float4 xv = xs[i];
        float a = ds[k];
        a = fmaf(xv.x, Ms[0 * HID + k], a);
        a = fmaf(xv.y, Ms[1 * HID + k], a);
        a = fmaf(xv.z, Ms[2 * HID + k], a);
        a = fmaf(xv.w, Ms[3 * HID + k], a);
        float c;
        c =      xv.x * Ms[4 * HID + k];
        c = fmaf(xv.y, Ms[5 * HID + k], c);
        c = fmaf(xv.z, Ms[6 * HID + k], c);
        c = fmaf(xv.w, Ms[7 * HID + k], c);
        Ab[k * NPTS + i] = a;    // coalesced (i fast)
        Cb[k * NPTS + i] = c;
    }
}

// ---------------------------------------------------------------------------
// Kernel 2: pair tiles.  16x16 (i,j) tiles, 64 threads, 2i x 2j per thread.
// Grid (36 tiles, 64 batches) = 2304 CTAs.
// ---------------------------------------------------------------------------
__global__ __launch_bounds__(64)
void pair_kernel(const float* __restrict__ W3,   // [100]
                 const float* __restrict__ b3,   // [1]
                 float* __restrict__ out)        // [64, 8128]
{
    __shared__ __align__(16) float aS[HID * 16];   // aS[k*16 + ii]
    __shared__ __align__(16) float cS[HID * 16];
    __shared__ float ws[HID];

    const int tid  = threadIdx.x;
    const int tile = blockIdx.x;
    const int b    = blockIdx.y;
    const int i0   = TCI[tile] * 16;
    const int j0   = TCJ[tile] * 16;

    const int tj = tid & 7;       // 8 j-groups of 2
    const int ti = tid >> 3;      // 8 i-groups of 2

    // --- prologue: pull A/C rows from L2 (float4, coalesced per k-row) ---
    const float* Ab = g_A + (size_t)b * (HID * NPTS) + i0;
    const float* Cb = g_C + (size_t)b * (HID * NPTS) + j0;
    for (int q = tid; q < 4 * HID; q += 64) {       // 400 float4s
        int k   = q >> 2;
        int ii4 = (q & 3) << 2;
        *reinterpret_cast<float4*>(aS + k * 16 + ii4) =
            *reinterpret_cast<const float4*>(Ab + k * NPTS + ii4);
        *reinterpret_cast<float4*>(cS + k * 16 + ii4) =
            *reinterpret_cast<const float4*>(Cb + k * NPTS + ii4);
    }
    for (int q = tid; q < HID; q += 64) ws[q] = W3[q];
    __syncthreads();

    // --- main loop: 2x2 slots, k contraction ---
    float acc0 = 0.f, acc1 = 0.f, acc2 = 0.f, acc3 = 0.f;
    const float* aP = aS + ti * 2;
    const float* cP = cS + tj * 2;

    #pragma unroll 4
    for (int k = 0; k < HID; k++) {
        float2 a2 = *reinterpret_cast<const float2*>(aP + k * 16);
        float2 c2 = *reinterpret_cast<const float2*>(cP + k * 16);
        float  w  = ws[k];
        acc0 = fmaf(fmaxf(a2.x + c2.x, 0.f), w, acc0);
        acc1 = fmaf(fmaxf(a2.x + c2.y, 0.f), w, acc1);
        acc2 = fmaf(fmaxf(a2.y + c2.x, 0.f), w, acc2);
        acc3 = fmaf(fmaxf(a2.y + c2.y, 0.f), w, acc3);
    }

    // --- epilogue: sigmoid + masked upper-triangular store ---
    const float bias3 = b3[0];
    float* outb = out + (size_t)b * NPAIRS;
    float accv[4] = {acc0, acc1, acc2, acc3};
    #pragma unroll
    for (int pi = 0; pi < 2; pi++) {
        int i  = i0 + ti * 2 + pi;
        int rb = i * (NPTS - 1) - ((i * (i - 1)) >> 1) - i - 1;
        #pragma unroll
        for (int pj = 0; pj < 2; pj++) {
            int j = j0 + tj * 2 + pj;
            if (j > i) {
                float v = bias3 + accv[pi * 2 + pj];
                outb[rb + j] = 1.f / (1.f + __expf(-v));
            }
        }
    }
}

// ---------------------------------------------------------------------------
extern "C" void kernel_launch(void* const* d_in, const int* in_sizes, int n_in,
                              void* d_out, int out_size)
{
    const float* x   = (const float*)d_in[0];
    // d_in[1] = in_hitnr (unused by the reference)
    const float* W1  = (const float*)d_in[2];
    const float* b1  = (const float*)d_in[3];
    const float* W2  = (const float*)d_in[4];
    const float* b2  = (const float*)d_in[5];
    const float* W3  = (const float*)d_in[6];
    const float* b3  = (const float*)d_in[7];
    float* out = (float*)d_out;

    precomp_kernel<<<BATCH, 256>>>(x, W1, b1, W2, b2);
    pair_kernel<<<dim3(36, BATCH), 64>>>(W3, b3, out);
}

// round 4
// speedup vs baseline: 1.0821x; 1.0821x over previous
#include <cuda_runtime.h>
#include <cuda_bf16.h>
#include <math.h>

#define BATCH  64
#define NPTS   128
#define FEAT   4
#define HID    100
#define NPAIRS 8128   // C(128,2)

// Per-point projections, k-major:
//   g_A[b][k][i] = d[k] + sum_f x[b][i][f] * M[f][k]     (bias folded)
//   g_C[b][k][j] =        sum_f x[b][j][f] * M[4+f][k]
// M[f][k] = sum_t W1[f][t]*W2[t][k],  d[k] = b2[k] + sum_t b1[t]*W2[t][k]
__device__ __align__(16) float g_A[BATCH * HID * NPTS];   // 3.125 MB
__device__ __align__(16) float g_C[BATCH * HID * NPTS];

// 32x32 tile list over the 4x4 upper triangle (jt >= it): 10 tiles
__constant__ unsigned char TCI[10] = {0,0,0,0, 1,1,1, 2,2, 3};
__constant__ unsigned char TCJ[10] = {0,1,2,3, 1,2,3, 2,3, 3};

// ---- packed f32x2 helpers (sm_100+) --------------------------------------
__device__ __forceinline__ unsigned long long f2_add(unsigned long long a,
                                                     unsigned long long b) {
    unsigned long long d;
    asm("add.rn.f32x2 %0, %1, %2;" : "=l"(d) : "l"(a), "l"(b));
    return d;
}
__device__ __forceinline__ unsigned long long f2_fma(unsigned long long a,
                                                     unsigned long long b,
                                                     unsigned long long c) {
    unsigned long long d;
    asm("fma.rn.f32x2 %0, %1, %2, %3;" : "=l"(d) : "l"(a), "l"(b), "l"(c));
    return d;
}
__device__ __forceinline__ unsigned long long f2_pack(float lo, float hi) {
    unsigned long long d;
    asm("mov.b64 %0, {%1, %2};" : "=l"(d) : "f"(lo), "f"(hi));
    return d;
}
__device__ __forceinline__ void f2_unpack(unsigned long long v, float& lo, float& hi) {
    asm("mov.b64 {%0, %1}, %2;" : "=f"(lo), "=f"(hi) : "l"(v));
}
__device__ __forceinline__ unsigned long long f2_relu(unsigned long long t) {
    float lo, hi;
    f2_unpack(t, lo, hi);
    lo = fmaxf(lo, 0.f);
    hi = fmaxf(hi, 0.f);
    return f2_pack(lo, hi);
}

// ---------------------------------------------------------------------------
// Kernel 1: fold (k-half) + per-point projection.  Grid (64 b, 2 k-halves).
// ---------------------------------------------------------------------------
__global__ __launch_bounds__(256)
void precomp_kernel(const float* __restrict__ x,    // [64,128,4]
                    const float* __restrict__ W1,   // [8,100]
                    const float* __restrict__ b1,   // [100]
                    const float* __restrict__ W2,   // [100,100]
                    const float* __restrict__ b2)   // [100]
{
    __shared__ __align__(16) float W2s[HID * HID];   // 40 KB
    __shared__ __align__(16) float W1s[8 * HID];
    __shared__ float b1s[HID];
    __shared__ float Ms[8 * 50];
    __shared__ float ds[50];
    __shared__ float4 xs[NPTS];

    const int tid = threadIdx.x;
    const int b   = blockIdx.x;
    const int k0  = blockIdx.y * 50;     // this CTA's k-half

    for (int q = tid; q < (HID * HID) / 4; q += 256)
        reinterpret_cast<float4*>(W2s)[q] = reinterpret_cast<const float4*>(W2)[q];
    for (int q = tid; q < (8 * HID) / 4; q += 256)
        reinterpret_cast<float4*>(W1s)[q] = reinterpret_cast<const float4*>(W1)[q];
    if (tid < HID) b1s[tid] = b1[tid];
    if (tid >= 128 && tid < 128 + NPTS)
        xs[tid - 128] = reinterpret_cast<const float4*>(x)[b * NPTS + (tid - 128)];
    __syncthreads();

    // fold this k-half: Ms[f][kk] = sum_t W1s[f][t]*W2s[t][k0+kk]
    for (int e = tid; e < 8 * 50; e += 256) {
        int f  = e / 50;
        int kk = e - f * 50;
        int k  = k0 + kk;
        float acc = 0.f;
        #pragma unroll 4
        for (int t = 0; t < HID; t++)
            acc = fmaf(W1s[f * HID + t], W2s[t * HID + k], acc);
        Ms[f * 50 + kk] = acc;
    }
    if (tid < 50) {
        int k = k0 + tid;
        float acc = 0.f;
        #pragma unroll 4
        for (int t = 0; t < HID; t++)
            acc = fmaf(b1s[t], W2s[t * HID + k], acc);
        ds[tid] = acc + b2[k];
    }
    __syncthreads();

    float* Ab = g_A + (size_t)b * (HID * NPTS);
    float* Cb = g_C + (size_t)b * (HID * NPTS);

    for (int e = tid; e < 50 * NPTS; e += 256) {
        int i  = e & (NPTS - 1);
        int kk = e >> 7;
        float4 xv = xs[i];
        float a = ds[kk];
        a = fmaf(xv.x, Ms[0 * 50 + kk], a);
        a = fmaf(xv.y, Ms[1 * 50 + kk], a);
        a = fmaf(xv.z, Ms[2 * 50 + kk], a);
        a = fmaf(xv.w, Ms[3 * 50 + kk], a);
        float c;
        c =      xv.x * Ms[4 * 50 + kk];
        c = fmaf(xv.y, Ms[5 * 50 + kk], c);
        c = fmaf(xv.z, Ms[6 * 50 + kk], c);
        c = fmaf(xv.w, Ms[7 * 50 + kk], c);
        Ab[(k0 + kk) * NPTS + i] = a;   // coalesced (i fast)
        Cb[(k0 + kk) * NPTS + i] = c;
    }
}

// ---------------------------------------------------------------------------
// Kernel 2: pair tiles.  32x32 (i,j) tiles, 64 threads, 4i x 4j per thread,
// packed f32x2 arithmetic.  Grid (10 tiles, 64 batches) = 640 CTAs.
// ---------------------------------------------------------------------------
__global__ __launch_bounds__(64)
void pair_kernel(const float* __restrict__ W3,   // [100]
                 const float* __restrict__ b3,   // [1]
                 float* __restrict__ out)        // [64, 8128]
{
    __shared__ __align__(16) float aS[HID * 32];   // [k][32]  12.8 KB
    __shared__ __align__(16) float cS[HID * 32];
    __shared__ __align__(8)  float2 wS[HID];       // (w,w) duplicated

    const int tid  = threadIdx.x;
    const int tile = blockIdx.x;
    const int b    = blockIdx.y;
    const int i0   = TCI[tile] * 32;
    const int j0   = TCJ[tile] * 32;

    const int tj = tid & 7;       // 8 j-groups of 4
    const int ti = tid >> 3;      // 8 i-groups of 4

    // --- prologue: stage A/C rows (float4, coalesced within each k-row) ---
    const float* Ab = g_A + (size_t)b * (HID * NPTS) + i0;
    const float* Cb = g_C + (size_t)b * (HID * NPTS) + j0;
    for (int q = tid; q < 8 * HID; q += 64) {       // 800 float4s
        int k = q >> 3;
        int m = (q & 7) << 2;
        *reinterpret_cast<float4*>(aS + k * 32 + m) =
            *reinterpret_cast<const float4*>(Ab + k * NPTS + m);
        *reinterpret_cast<float4*>(cS + k * 32 + m) =
            *reinterpret_cast<const float4*>(Cb + k * NPTS + m);
    }
    for (int q = tid; q < HID; q += 64) {
        float w = W3[q];
        wS[q] = make_float2(w, w);
    }
    __syncthreads();

    // --- main loop: 16 slots per thread, packed f32x2 ---
    // acc[jr*2+0] holds (i0', i0'+1) for j = j0'+jr;  acc[jr*2+1] holds (+2,+3)
    unsigned long long acc[8] = {0ull,0ull,0ull,0ull,0ull,0ull,0ull,0ull};
    const float* aP = aS + ti * 4;
    const float* cP = cS + tj * 4;
    const unsigned long long* wP = reinterpret_cast<const unsigned long long*>(wS);

    #pragma unroll 2
    for (int k = 0; k < HID; k++) {
        float4 a4 = *reinterpret_cast<const float4*>(aP + k * 32);  // LDS.128
        float4 c4 = *reinterpret_cast<const float4*>(cP + k * 32);  // LDS.128
        unsigned long long w2 = wP[k];                               // LDS.64 bcast
        unsigned long long A01 = f2_pack(a4.x, a4.y);
        unsigned long long A23 = f2_pack(a4.z, a4.w);
        const float cj[4] = {c4.x, c4.y, c4.z, c4.w};
        #pragma unroll
        for (int jr = 0; jr < 4; jr++) {
            unsigned long long cd = f2_pack(cj[jr], cj[jr]);
            unsigned long long t0 = f2_relu(f2_add(A01, cd));
            unsigned long long t1 = f2_relu(f2_add(A23, cd));
            acc[jr * 2 + 0] = f2_fma(t0, w2, acc[jr * 2 + 0]);
            acc[jr * 2 + 1] = f2_fma(t1, w2, acc[jr * 2 + 1]);
        }
    }

    // --- epilogue: sigmoid + masked upper-triangular store ---
    const float bias3 = b3[0];
    float* outb = out + (size_t)b * NPAIRS;
    #pragma unroll
    for (int jr = 0; jr < 4; jr++) {
        int j = j0 + tj * 4 + jr;
        float v[4];
        f2_unpack(acc[jr * 2 + 0], v[0], v[1]);
        f2_unpack(acc[jr * 2 + 1], v[2], v[3]);
        #pragma unroll
        for (int pi = 0; pi < 4; pi++) {
            int i = i0 + ti * 4 + pi;
            if (j > i) {
                int rb = i * (NPTS - 1) - ((i * (i - 1)) >> 1) - i - 1;
                float s = bias3 + v[pi];
                outb[rb + j] = __fdividef(1.f, 1.f + __expf(-s));
            }
        }
    }
}

// ---------------------------------------------------------------------------
extern "C" void kernel_launch(void* const* d_in, const int* in_sizes, int n_in,
                              void* d_out, int out_size)
{
    const float* x   = (const float*)d_in[0];
    // d_in[1] = in_hitnr (unused by the reference)
    const float* W1  = (const float*)d_in[2];
    const float* b1  = (const float*)d_in[3];
    const float* W2  = (const float*)d_in[4];
    const float* b2  = (const float*)d_in[5];
    const float* W3  = (const float*)d_in[6];
    const float* b3  = (const float*)d_in[7];
    float* out = (float*)d_out;

    precomp_kernel<<<dim3(BATCH, 2), 256>>>(x, W1, b1, W2, b2);
    pair_kernel<<<dim3(10, BATCH), 64>>>(W3, b3, out);
}

// round 5
// speedup vs baseline: 1.1756x; 1.0864x over previous
#include <cuda_runtime.h>
#include <cuda_bf16.h>
#include <math.h>

#define BATCH  64
#define NPTS   128
#define FEAT   4
#define HID    100
#define NPAIRS 8128   // C(128,2)

// Per-point projections, k-major:
//   g_A[b][k][i] = d[k] + sum_f x[b][i][f] * M[f][k]     (bias folded)
//   g_C[b][k][j] =        sum_f x[b][j][f] * M[4+f][k]
__device__ __align__(16) float g_A[BATCH * HID * NPTS];   // 3.125 MB
__device__ __align__(16) float g_C[BATCH * HID * NPTS];

// 32x32 tile list over the 4x4 upper triangle (jt >= it): 10 tiles
__constant__ unsigned char TCI[10] = {0,0,0,0, 1,1,1, 2,2, 3};
__constant__ unsigned char TCJ[10] = {0,1,2,3, 1,2,3, 2,3, 3};

// ---- packed f32x2 helpers (sm_100+) --------------------------------------
__device__ __forceinline__ unsigned long long f2_add(unsigned long long a,
                                                     unsigned long long b) {
    unsigned long long d;
    asm("add.rn.f32x2 %0, %1, %2;" : "=l"(d) : "l"(a), "l"(b));
    return d;
}
__device__ __forceinline__ unsigned long long f2_fma(unsigned long long a,
                                                     unsigned long long b,
                                                     unsigned long long c) {
    unsigned long long d;
    asm("fma.rn.f32x2 %0, %1, %2, %3;" : "=l"(d) : "l"(a), "l"(b), "l"(c));
    return d;
}
__device__ __forceinline__ unsigned long long f2_pack(float lo, float hi) {
    unsigned long long d;
    asm("mov.b64 %0, {%1, %2};" : "=l"(d) : "f"(lo), "f"(hi));
    return d;
}
__device__ __forceinline__ void f2_unpack(unsigned long long v, float& lo, float& hi) {
    asm("mov.b64 {%0, %1}, %2;" : "=f"(lo), "=f"(hi) : "l"(v));
}
__device__ __forceinline__ unsigned long long f2_relu(unsigned long long t) {
    float lo, hi;
    f2_unpack(t, lo, hi);
    lo = fmaxf(lo, 0.f);
    hi = fmaxf(hi, 0.f);
    return f2_pack(lo, hi);
}

// ---------------------------------------------------------------------------
// Kernel 1: fold (k-half) + per-point projection.  Grid (64 b, 2 k-halves).
// ---------------------------------------------------------------------------
__global__ __launch_bounds__(256)
void precomp_kernel(const float* __restrict__ x,    // [64,128,4]
                    const float* __restrict__ W1,   // [8,100]
                    const float* __restrict__ b1,   // [100]
                    const float* __restrict__ W2,   // [100,100]
                    const float* __restrict__ b2)   // [100]
{
    __shared__ __align__(16) float W2s[HID * HID];   // 40 KB
    __shared__ __align__(16) float W1s[8 * HID];
    __shared__ float b1s[HID];
    __shared__ float Ms[8 * 50];
    __shared__ float ds[50];
    __shared__ float4 xs[NPTS];

    const int tid = threadIdx.x;
    const int b   = blockIdx.x;
    const int k0  = blockIdx.y * 50;     // this CTA's k-half

    for (int q = tid; q < (HID * HID) / 4; q += 256)
        reinterpret_cast<float4*>(W2s)[q] = reinterpret_cast<const float4*>(W2)[q];
    for (int q = tid; q < (8 * HID) / 4; q += 256)
        reinterpret_cast<float4*>(W1s)[q] = reinterpret_cast<const float4*>(W1)[q];
    if (tid < HID) b1s[tid] = b1[tid];
    if (tid >= 128 && tid < 128 + NPTS)
        xs[tid - 128] = reinterpret_cast<const float4*>(x)[b * NPTS + (tid - 128)];
    __syncthreads();

    // fold this k-half: Ms[f][kk] = sum_t W1s[f][t]*W2s[t][k0+kk]
    for (int e = tid; e < 8 * 50; e += 256) {
        int f  = e / 50;
        int kk = e - f * 50;
        int k  = k0 + kk;
        float acc = 0.f;
        #pragma unroll 4
        for (int t = 0; t < HID; t++)
            acc = fmaf(W1s[f * HID + t], W2s[t * HID + k], acc);
        Ms[f * 50 + kk] = acc;
    }
    if (tid < 50) {
        int k = k0 + tid;
        float acc = 0.f;
        #pragma unroll 4
        for (int t = 0; t < HID; t++)
            acc = fmaf(b1s[t], W2s[t * HID + k], acc);
        ds[tid] = acc + b2[k];
    }
    __syncthreads();

    float* Ab = g_A + (size_t)b * (HID * NPTS);
    float* Cb = g_C + (size_t)b * (HID * NPTS);

    for (int e = tid; e < 50 * NPTS; e += 256) {
        int i  = e & (NPTS - 1);
        int kk = e >> 7;
        float4 xv = xs[i];
        float a = ds[kk];
        a = fmaf(xv.x, Ms[0 * 50 + kk], a);
        a = fmaf(xv.y, Ms[1 * 50 + kk], a);
        a = fmaf(xv.z, Ms[2 * 50 + kk], a);
        a = fmaf(xv.w, Ms[3 * 50 + kk], a);
        float c;
        c =      xv.x * Ms[4 * 50 + kk];
        c = fmaf(xv.y, Ms[5 * 50 + kk], c);
        c = fmaf(xv.z, Ms[6 * 50 + kk], c);
        c = fmaf(xv.w, Ms[7 * 50 + kk], c);
        Ab[(k0 + kk) * NPTS + i] = a;   // coalesced (i fast)
        Cb[(k0 + kk) * NPTS + i] = c;
    }
}

// ---------------------------------------------------------------------------
// Kernel 2: pair tiles.  32x32 tile, 256 threads = 4 k-groups x 64 threads.
// Each 64-thread group: 4i x 4j slots per thread, contracts 25 k's.
// Smem reduction combines the 4 partials; group 0 stores.
// Grid (10 tiles, 64 batches) = 640 CTAs, 8 warps each -> ~35 warps/SM.
// ---------------------------------------------------------------------------
__global__ __launch_bounds__(256, 5)
void pair_kernel(const float* __restrict__ W3,   // [100]
                 const float* __restrict__ b3,   // [1]
                 float* __restrict__ out)        // [64, 8128]
{
    __shared__ __align__(16) float aS[HID * 32];          // 12.8 KB
    __shared__ __align__(16) float cS[HID * 32];          // 12.8 KB
    __shared__ __align__(8)  float2 wS[HID];              // (w,w) dup
    __shared__ __align__(16) unsigned long long redS[8 * 192];  // 12 KB

    const int tid  = threadIdx.x;
    const int tile = blockIdx.x;
    const int b    = blockIdx.y;
    const int i0   = TCI[tile] * 32;
    const int j0   = TCJ[tile] * 32;

    const int kg  = tid >> 6;        // k-group 0..3
    const int t64 = tid & 63;
    const int tj  = t64 & 7;         // 8 j-groups of 4
    const int ti  = t64 >> 3;        // 8 i-groups of 4

    // --- prologue: stage A/C rows (float4, coalesced within each k-row) ---
    const float* Ab = g_A + (size_t)b * (HID * NPTS) + i0;
    const float* Cb = g_C + (size_t)b * (HID * NPTS) + j0;
    for (int q = tid; q < 8 * HID; q += 256) {       // 800 float4s
        int k = q >> 3;
        int m = (q & 7) << 2;
        *reinterpret_cast<float4*>(aS + k * 32 + m) =
            *reinterpret_cast<const float4*>(Ab + k * NPTS + m);
        *reinterpret_cast<float4*>(cS + k * 32 + m) =
            *reinterpret_cast<const float4*>(Cb + k * NPTS + m);
    }
    for (int q = tid; q < HID; q += 256) {
        float w = W3[q];
        wS[q] = make_float2(w, w);
    }
    __syncthreads();

    // --- main loop: 16 slots per thread, 25 k's per group, packed f32x2 ---
    unsigned long long acc[8] = {0ull,0ull,0ull,0ull,0ull,0ull,0ull,0ull};
    const float* aP = aS + ti * 4;
    const float* cP = cS + tj * 4;
    const unsigned long long* wP = reinterpret_cast<const unsigned long long*>(wS);
    const int kEnd = kg * 25 + 25;

    #pragma unroll 5
    for (int k = kg * 25; k < kEnd; k++) {
        float4 a4 = *reinterpret_cast<const float4*>(aP + k * 32);  // LDS.128
        float4 c4 = *reinterpret_cast<const float4*>(cP + k * 32);  // LDS.128
        unsigned long long w2 = wP[k];                               // LDS.64 bcast
        unsigned long long A01 = f2_pack(a4.x, a4.y);   // free (aligned quad)
        unsigned long long A23 = f2_pack(a4.z, a4.w);
        const float cj[4] = {c4.x, c4.y, c4.z, c4.w};
        #pragma unroll
        for (int jr = 0; jr < 4; jr++) {
            unsigned long long cd = f2_pack(cj[jr], cj[jr]);
            unsigned long long t0 = f2_relu(f2_add(A01, cd));
            unsigned long long t1 = f2_relu(f2_add(A23, cd));
            acc[jr * 2 + 0] = f2_fma(t0, w2, acc[jr * 2 + 0]);
            acc[jr * 2 + 1] = f2_fma(t1, w2, acc[jr * 2 + 1]);
        }
    }

    // --- combine partials: groups 1..3 write (conflict-free stride), group 0 adds ---
    if (kg > 0) {
        #pragma unroll
        for (int q = 0; q < 8; q++)
            redS[q * 192 + (kg - 1) * 64 + t64] = acc[q];
    }
    __syncthreads();

    if (kg == 0) {
        #pragma unroll
        for (int q = 0; q < 8; q++) {
            acc[q] = f2_add(acc[q], redS[q * 192 +   0 + t64]);
            acc[q] = f2_add(acc[q], redS[q * 192 +  64 + t64]);
            acc[q] = f2_add(acc[q], redS[q * 192 + 128 + t64]);
        }

        // --- epilogue: sigmoid + masked upper-triangular store ---
        const float bias3 = b3[0];
        float* outb = out + (size_t)b * NPAIRS;
        #pragma unroll
        for (int jr = 0; jr < 4; jr++) {
            int j = j0 + tj * 4 + jr;
            float v[4];
            f2_unpack(acc[jr * 2 + 0], v[0], v[1]);
            f2_unpack(acc[jr * 2 + 1], v[2], v[3]);
            #pragma unroll
            for (int pi = 0; pi < 4; pi++) {
                int i = i0 + ti * 4 + pi;
                if (j > i) {
                    int rb = i * (NPTS - 1) - ((i * (i - 1)) >> 1) - i - 1;
                    float s = bias3 + v[pi];
                    outb[rb + j] = __fdividef(1.f, 1.f + __expf(-s));
                }
            }
        }
    }
}

// ---------------------------------------------------------------------------
extern "C" void kernel_launch(void* const* d_in, const int* in_sizes, int n_in,
                              void* d_out, int out_size)
{
    const float* x   = (const float*)d_in[0];
    // d_in[1] = in_hitnr (unused by the reference)
    const float* W1  = (const float*)d_in[2];
    const float* b1  = (const float*)d_in[3];
    const float* W2  = (const float*)d_in[4];
    const float* b2  = (const float*)d_in[5];
    const float* W3  = (const float*)d_in[6];
    const float* b3  = (const float*)d_in[7];
    float* out = (float*)d_out;

    precomp_kernel<<<dim3(BATCH, 2), 256>>>(x, W1, b1, W2, b2);
    pair_kernel<<<dim3(10, BATCH), 256>>>(W3, b3, out);
}

// round 6
// speedup vs baseline: 1.4283x; 1.2150x over previous
#include <cuda_runtime.h>
#include <cuda_bf16.h>
#include <math.h>

#define BATCH  64
#define NPTS   128
#define FEAT   4
#define HID    100
#define NPAIRS 8128   // C(128,2)

// Folded weights: g_M[f][k] = sum_t W1[f][t]*W2[t][k] (f 0..7)
//                 g_d[k]    = b2[k] + sum_t b1[t]*W2[t][k]
__device__ __align__(16) float g_M[8 * HID];
__device__ __align__(16) float g_d[HID];

// 32x32 tile list over the 4x4 upper triangle (jt >= it): 10 tiles
__constant__ unsigned char TCI[10] = {0,0,0,0, 1,1,1, 2,2, 3};
__constant__ unsigned char TCJ[10] = {0,1,2,3, 1,2,3, 2,3, 3};

// ---- packed f32x2 helpers (sm_100+) --------------------------------------
__device__ __forceinline__ unsigned long long f2_add(unsigned long long a,
                                                     unsigned long long b) {
    unsigned long long d;
    asm("add.rn.f32x2 %0, %1, %2;" : "=l"(d) : "l"(a), "l"(b));
    return d;
}
__device__ __forceinline__ unsigned long long f2_fma(unsigned long long a,
                                                     unsigned long long b,
                                                     unsigned long long c) {
    unsigned long long d;
    asm("fma.rn.f32x2 %0, %1, %2, %3;" : "=l"(d) : "l"(a), "l"(b), "l"(c));
    return d;
}
__device__ __forceinline__ unsigned long long f2_pack(float lo, float hi) {
    unsigned long long d;
    asm("mov.b64 %0, {%1, %2};" : "=l"(d) : "f"(lo), "f"(hi));
    return d;
}
__device__ __forceinline__ void f2_unpack(unsigned long long v, float& lo, float& hi) {
    asm("mov.b64 {%0, %1}, %2;" : "=f"(lo), "=f"(hi) : "l"(v));
}
__device__ __forceinline__ unsigned long long f2_relu(unsigned long long t) {
    float lo, hi;
    f2_unpack(t, lo, hi);
    lo = fmaxf(lo, 0.f);
    hi = fmaxf(hi, 0.f);
    return f2_pack(lo, hi);
}

// ---------------------------------------------------------------------------
// Kernel 1: fold.  One warp per k (grid 100).  Lane-strided t, shfl-reduce.
// High MLP (4 outstanding strided W2 loads per lane) hides cold DRAM.
// ---------------------------------------------------------------------------
__global__ __launch_bounds__(32)
void fold_kernel(const float* __restrict__ W1,   // [8,100]
                 const float* __restrict__ b1,   // [100]
                 const float* __restrict__ W2,   // [100,100]
                 const float* __restrict__ b2)   // [100]
{
    const int k   = blockIdx.x;
    const int lid = threadIdx.x;

    float acc[9] = {0.f,0.f,0.f,0.f,0.f,0.f,0.f,0.f,0.f};
    #pragma unroll
    for (int tb = 0; tb < 4; tb++) {
        int t = lid + tb * 32;
        if (t < HID) {
            float w2 = W2[t * HID + k];
            #pragma unroll
            for (int f = 0; f < 8; f++)
                acc[f] = fmaf(W1[f * HID + t], w2, acc[f]);
            acc[8] = fmaf(b1[t], w2, acc[8]);
        }
    }
    #pragma unroll
    for (int off = 16; off > 0; off >>= 1) {
        #pragma unroll
        for (int q = 0; q < 9; q++)
            acc[q] += __shfl_down_sync(0xffffffffu, acc[q], off);
    }
    if (lid == 0) {
        #pragma unroll
        for (int f = 0; f < 8; f++)
            g_M[f * HID + k] = acc[f];
        g_d[k] = acc[8] + b2[k];
    }
}

// ---------------------------------------------------------------------------
// Kernel 2: pair tiles with fused projection.
// 32x32 tile, 256 threads = 4 k-groups x 64.  4i x 4j f32x2 slots per thread.
// Prologue computes aS/cS directly from x and g_M (no global A/C round trip).
// Grid (10 tiles, 64 batches) = 640 CTAs, 37.8 KB smem -> 5 CTAs/SM, 1 wave.
// ---------------------------------------------------------------------------
__global__ __launch_bounds__(256, 5)
void pair_kernel(const float* __restrict__ x,    // [64,128,4]
                 const float* __restrict__ W3,   // [100]
                 const float* __restrict__ b3,   // [1]
                 float* __restrict__ out)        // [64, 8128]
{
    __shared__ __align__(16) float aS[HID * 32];               // 12.8 KB
    __shared__ __align__(16) float cS[HID * 32];               // 12.8 KB
    __shared__ __align__(8)  float2 wS[HID];                   // 0.8 KB
    __shared__ __align__(16) unsigned long long redS[8 * 192]; // 12 KB

    // Prologue-only data aliased into redS storage (redS is used strictly
    // after the main loop; a __syncthreads separates the two uses).
    float*  Ms = reinterpret_cast<float*>(redS);               // 800 floats
    float4* xi = reinterpret_cast<float4*>(redS + 512);        // 32 float4
    float4* xj = xi + 32;                                      // 32 float4
    float*  ds = reinterpret_cast<float*>(redS + 640);         // 100 floats

    const int tid  = threadIdx.x;
    const int tile = blockIdx.x;
    const int b    = blockIdx.y;
    const int i0   = TCI[tile] * 32;
    const int j0   = TCJ[tile] * 32;

    const int kg  = tid >> 6;        // k-group 0..3
    const int t64 = tid & 63;
    const int tj  = t64 & 7;         // 8 j-groups of 4
    const int ti  = t64 >> 3;        // 8 i-groups of 4

    // --- stage M, d, x tiles, w ---
    for (int q = tid; q < 200; q += 256)
        reinterpret_cast<float4*>(Ms)[q] = reinterpret_cast<const float4*>(g_M)[q];
    if (tid < 32)            xi[tid]      = reinterpret_cast<const float4*>(x)[b * NPTS + i0 + tid];
    else if (tid < 64)       xj[tid - 32] = reinterpret_cast<const float4*>(x)[b * NPTS + j0 + (tid - 32)];
    else if (tid < 64 + HID) ds[tid - 64] = g_d[tid - 64];
    if (tid >= 192 - HID && tid < 192) {
        int q = tid - (192 - HID);
        float w = W3[q];
        wS[q] = make_float2(w, w);
    }
    __syncthreads();

    // --- projection: aS[k][ii] = d[k] + x_i . M[0:4][k];  cS likewise ---
    for (int e = tid; e < 32 * HID; e += 256) {
        int k  = e >> 5;
        int ii = e & 31;
        float4 xv = xi[ii];
        float a = ds[k];
        a = fmaf(xv.x, Ms[0 * HID + k], a);
        a = fmaf(xv.y, Ms[1 * HID + k], a);
        a = fmaf(xv.z, Ms[2 * HID + k], a);
        a = fmaf(xv.w, Ms[3 * HID + k], a);
        aS[k * 32 + ii] = a;
        float4 xw = xj[ii];
        float c;
        c =      xw.x * Ms[4 * HID + k];
        c = fmaf(xw.y, Ms[5 * HID + k], c);
        c = fmaf(xw.z, Ms[6 * HID + k], c);
        c = fmaf(xw.w, Ms[7 * HID + k], c);
        cS[k * 32 + ii] = c;
    }
    __syncthreads();   // also fences the redS aliasing

    // --- main loop: 16 slots per thread, 25 k's per group, packed f32x2 ---
    unsigned long long acc[8] = {0ull,0ull,0ull,0ull,0ull,0ull,0ull,0ull};
    const float* aP = aS + ti * 4;
    const float* cP = cS + tj * 4;
    const unsigned long long* wP = reinterpret_cast<const unsigned long long*>(wS);
    const int kEnd = kg * 25 + 25;

    #pragma unroll 5
    for (int k = kg * 25; k < kEnd; k++) {
        float4 a4 = *reinterpret_cast<const float4*>(aP + k * 32);  // LDS.128
        float4 c4 = *reinterpret_cast<const float4*>(cP + k * 32);  // LDS.128
        unsigned long long w2 = wP[k];                               // LDS.64 bcast
        unsigned long long A01 = f2_pack(a4.x, a4.y);
        unsigned long long A23 = f2_pack(a4.z, a4.w);
        const float cj[4] = {c4.x, c4.y, c4.z, c4.w};
        #pragma unroll
        for (int jr = 0; jr < 4; jr++) {
            unsigned long long cd = f2_pack(cj[jr], cj[jr]);
            unsigned long long t0 = f2_relu(f2_add(A01, cd));
            unsigned long long t1 = f2_relu(f2_add(A23, cd));
            acc[jr * 2 + 0] = f2_fma(t0, w2, acc[jr * 2 + 0]);
            acc[jr * 2 + 1] = f2_fma(t1, w2, acc[jr * 2 + 1]);
        }
    }

    // --- combine partials (conflict-free stride), group 0 finishes ---
    if (kg > 0) {
        #pragma unroll
        for (int q = 0; q < 8; q++)
            redS[q * 192 + (kg - 1) * 64 + t64] = acc[q];
    }
    __syncthreads();

    if (kg == 0) {
        #pragma unroll
        for (int q = 0; q < 8; q++) {
            acc[q] = f2_add(acc[q], redS[q * 192 +   0 + t64]);
            acc[q] = f2_add(acc[q], redS[q * 192 +  64 + t64]);
            acc[q] = f2_add(acc[q], redS[q * 192 + 128 + t64]);
        }

        const float bias3 = b3[0];
        float* outb = out + (size_t)b * NPAIRS;
        #pragma unroll
        for (int jr = 0; jr < 4; jr++) {
            int j = j0 + tj * 4 + jr;
            float v[4];
            f2_unpack(acc[jr * 2 + 0], v[0], v[1]);
            f2_unpack(acc[jr * 2 + 1], v[2], v[3]);
            #pragma unroll
            for (int pi = 0; pi < 4; pi++) {
                int i = i0 + ti * 4 + pi;
                if (j > i) {
                    int rb = i * (NPTS - 1) - ((i * (i - 1)) >> 1) - i - 1;
                    float s = bias3 + v[pi];
                    outb[rb + j] = __fdividef(1.f, 1.f + __expf(-s));
                }
            }
        }
    }
}

// ---------------------------------------------------------------------------
extern "C" void kernel_launch(void* const* d_in, const int* in_sizes, int n_in,
                              void* d_out, int out_size)
{
    const float* x   = (const float*)d_in[0];
    // d_in[1] = in_hitnr (unused by the reference)
    const float* W1  = (const float*)d_in[2];
    const float* b1  = (const float*)d_in[3];
    const float* W2  = (const float*)d_in[4];
    const float* b2  = (const float*)d_in[5];
    const float* W3  = (const float*)d_in[6];
    const float* b3  = (const float*)d_in[7];
    float* out = (float*)d_out;

    fold_kernel<<<HID, 32>>>(W1, b1, W2, b2);
    pair_kernel<<<dim3(10, BATCH), 256>>>(x, W3, b3, out);
}

// round 7
// speedup vs baseline: 1.6262x; 1.1385x over previous
#include <cuda_runtime.h>
#include <cuda_bf16.h>
#include <math.h>

#define BATCH  64
#define NPTS   128
#define FEAT   4
#define HID    100
#define NPAIRS 8128   // C(128,2)

// Folded weights: g_M[f][k] = sum_t W1[f][t]*W2[t][k] (f 0..7)
//                 g_d[k]    = b2[k] + sum_t b1[t]*W2[t][k]
__device__ __align__(16) float g_M[8 * HID];
__device__ __align__(16) float g_d[HID];

// 32x32 tile list over the 4x4 upper triangle (jt >= it): 10 tiles
__constant__ unsigned char TCI[10] = {0,0,0,0, 1,1,1, 2,2, 3};
__constant__ unsigned char TCJ[10] = {0,1,2,3, 1,2,3, 2,3, 3};

// ---- packed f32x2 helpers (sm_100+) --------------------------------------
__device__ __forceinline__ unsigned long long f2_add(unsigned long long a,
                                                     unsigned long long b) {
    unsigned long long d;
    asm("add.rn.f32x2 %0, %1, %2;" : "=l"(d) : "l"(a), "l"(b));
    return d;
}
__device__ __forceinline__ unsigned long long f2_fma(unsigned long long a,
                                                     unsigned long long b,
                                                     unsigned long long c) {
    unsigned long long d;
    asm("fma.rn.f32x2 %0, %1, %2, %3;" : "=l"(d) : "l"(a), "l"(b), "l"(c));
    return d;
}
__device__ __forceinline__ unsigned long long f2_pack(float lo, float hi) {
    unsigned long long d;
    asm("mov.b64 %0, {%1, %2};" : "=l"(d) : "f"(lo), "f"(hi));
    return d;
}
__device__ __forceinline__ void f2_unpack(unsigned long long v, float& lo, float& hi) {
    asm("mov.b64 {%0, %1}, %2;" : "=f"(lo), "=f"(hi) : "l"(v));
}
__device__ __forceinline__ unsigned long long f2_relu(unsigned long long t) {
    float lo, hi;
    f2_unpack(t, lo, hi);
    lo = fmaxf(lo, 0.f);
    hi = fmaxf(hi, 0.f);
    return f2_pack(lo, hi);
}

// ---------------------------------------------------------------------------
// Kernel 1: fold.  One warp per k (grid 100).  Lane-strided t, shfl-reduce.
// ---------------------------------------------------------------------------
__global__ __launch_bounds__(32)
void fold_kernel(const float* __restrict__ W1,   // [8,100]
                 const float* __restrict__ b1,   // [100]
                 const float* __restrict__ W2,   // [100,100]
                 const float* __restrict__ b2)   // [100]
{
    const int k   = blockIdx.x;
    const int lid = threadIdx.x;

    float acc[9] = {0.f,0.f,0.f,0.f,0.f,0.f,0.f,0.f,0.f};
    #pragma unroll
    for (int tb = 0; tb < 4; tb++) {
        int t = lid + tb * 32;
        if (t < HID) {
            float w2 = W2[t * HID + k];
            #pragma unroll
            for (int f = 0; f < 8; f++)
                acc[f] = fmaf(W1[f * HID + t], w2, acc[f]);
            acc[8] = fmaf(b1[t], w2, acc[8]);
        }
    }
    #pragma unroll
    for (int off = 16; off > 0; off >>= 1) {
        #pragma unroll
        for (int q = 0; q < 9; q++)
            acc[q] += __shfl_down_sync(0xffffffffu, acc[q], off);
    }
    if (lid == 0) {
        #pragma unroll
        for (int f = 0; f < 8; f++)
            g_M[f * HID + k] = acc[f];
        g_d[k] = acc[8] + b2[k];
    }
}

// ---------------------------------------------------------------------------
// Kernel 2: pair tiles with fused projection.
// 32x32 tile, 256 threads = 4 k-groups x 64.  4i x 4j f32x2 slots per thread.
// Register-blocked projection prologue; all-groups reduction + distributed
// epilogue.  Grid (10 tiles, 64 batches) = 640 CTAs, ~41.8 KB -> 5 CTAs/SM.
// ---------------------------------------------------------------------------
__global__ __launch_bounds__(256, 5)
void pair_kernel(const float* __restrict__ x,    // [64,128,4]
                 const float* __restrict__ W3,   // [100]
                 const float* __restrict__ b3,   // [1]
                 float* __restrict__ out)        // [64, 8128]
{
    __shared__ __align__(16) float aS[HID * 32];                // 12.8 KB
    __shared__ __align__(16) float cS[HID * 32];                // 12.8 KB
    __shared__ __align__(8)  float2 wS[HID];                    // 0.8 KB
    __shared__ __align__(16) unsigned long long redS[8 * 256];  // 16 KB

    // Prologue-only data aliased into redS (redS used strictly post-mainloop).
    float*  Ms = reinterpret_cast<float*>(redS);               // u64[0..400)
    float4* xi = reinterpret_cast<float4*>(redS + 512);        // 32 float4
    float4* xj = xi + 32;                                      // 32 float4
    float*  ds = reinterpret_cast<float*>(redS + 704);         // 100 floats

    const int tid  = threadIdx.x;
    const int tile = blockIdx.x;
    const int b    = blockIdx.y;
    const int i0   = TCI[tile] * 32;
    const int j0   = TCJ[tile] * 32;

    const int kg  = tid >> 6;        // k-group 0..3
    const int t64 = tid & 63;
    const int tj  = t64 & 7;         // 8 j-groups of 4
    const int ti  = t64 >> 3;        // 8 i-groups of 4

    // --- stage M, d, x tiles, w ---
    for (int q = tid; q < 200; q += 256)
        reinterpret_cast<float4*>(Ms)[q] = reinterpret_cast<const float4*>(g_M)[q];
    if (tid < 32)            xi[tid]      = reinterpret_cast<const float4*>(x)[b * NPTS + i0 + tid];
    else if (tid < 64)       xj[tid - 32] = reinterpret_cast<const float4*>(x)[b * NPTS + j0 + (tid - 32)];
    else if (tid < 89)       reinterpret_cast<float4*>(ds)[tid - 64] =
                                 reinterpret_cast<const float4*>(g_d)[tid - 64];
    if (tid >= 128 && tid < 128 + HID) {
        int q = tid - 128;
        float w = W3[q];
        wS[q] = make_float2(w, w);
    }
    __syncthreads();

    // --- projection, register-blocked: thread = (k-quad, point ii) ---
    // aS[k][ii] = d[k] + x_i . M[0:4][k];  cS[k][ii] = x_j . M[4:8][k]
    {
        const float4* Ms4 = reinterpret_cast<const float4*>(Ms);
        const float4* ds4 = reinterpret_cast<const float4*>(ds);
        for (int e = tid; e < 25 * 32; e += 256) {
            int kq = e >> 5;          // k-quad 0..24
            int ii = e & 31;
            float4 xv = xi[ii];
            float4 xw = xj[ii];
            float4 a  = ds4[kq];
            float4 c  = make_float4(0.f, 0.f, 0.f, 0.f);
            float4 m;
            m = Ms4[0 * 25 + kq];
            a.x = fmaf(xv.x, m.x, a.x); a.y = fmaf(xv.x, m.y, a.y);
            a.z = fmaf(xv.x, m.z, a.z); a.w = fmaf(xv.x, m.w, a.w);
            m = Ms4[1 * 25 + kq];
            a.x = fmaf(xv.y, m.x, a.x); a.y = fmaf(xv.y, m.y, a.y);
            a.z = fmaf(xv.y, m.z, a.z); a.w = fmaf(xv.y, m.w, a.w);
            m = Ms4[2 * 25 + kq];
            a.x = fmaf(xv.z, m.x, a.x); a.y = fmaf(xv.z, m.y, a.y);
            a.z = fmaf(xv.z, m.z, a.z); a.w = fmaf(xv.z, m.w, a.w);
            m = Ms4[3 * 25 + kq];
            a.x = fmaf(xv.w, m.x, a.x); a.y = fmaf(xv.w, m.y, a.y);
            a.z = fmaf(xv.w, m.z, a.z); a.w = fmaf(xv.w, m.w, a.w);
            m = Ms4[4 * 25 + kq];
            c.x = fmaf(xw.x, m.x, c.x); c.y = fmaf(xw.x, m.y, c.y);
            c.z = fmaf(xw.x, m.z, c.z); c.w = fmaf(xw.x, m.w, c.w);
            m = Ms4[5 * 25 + kq];
            c.x = fmaf(xw.y, m.x, c.x); c.y = fmaf(xw.y, m.y, c.y);
            c.z = fmaf(xw.y, m.z, c.z); c.w = fmaf(xw.y, m.w, c.w);
            m = Ms4[6 * 25 + kq];
            c.x = fmaf(xw.z, m.x, c.x); c.y = fmaf(xw.z, m.y, c.y);
            c.z = fmaf(xw.z, m.z, c.z); c.w = fmaf(xw.z, m.w, c.w);
            m = Ms4[7 * 25 + kq];
            c.x = fmaf(xw.w, m.x, c.x); c.y = fmaf(xw.w, m.y, c.y);
            c.z = fmaf(xw.w, m.z, c.z); c.w = fmaf(xw.w, m.w, c.w);
            int base = kq * 128 + ii;           // (4kq)*32 + ii
            aS[base      ] = a.x;  aS[base + 32] = a.y;
            aS[base +  64] = a.z;  aS[base + 96] = a.w;
            cS[base      ] = c.x;  cS[base + 32] = c.y;
            cS[base +  64] = c.z;  cS[base + 96] = c.w;
        }
    }
    __syncthreads();   // also fences the redS aliasing

    // --- main loop: 16 slots per thread, 25 k's per group, packed f32x2 ---
    unsigned long long acc[8] = {0ull,0ull,0ull,0ull,0ull,0ull,0ull,0ull};
    const float* aP = aS + ti * 4;
    const float* cP = cS + tj * 4;
    const unsigned long long* wP = reinterpret_cast<const unsigned long long*>(wS);
    const int kEnd = kg * 25 + 25;

    #pragma unroll 5
    for (int k = kg * 25; k < kEnd; k++) {
        float4 a4 = *reinterpret_cast<const float4*>(aP + k * 32);  // LDS.128
        float4 c4 = *reinterpret_cast<const float4*>(cP + k * 32);  // LDS.128
        unsigned long long w2 = wP[k];                               // LDS.64 bcast
        unsigned long long A01 = f2_pack(a4.x, a4.y);
        unsigned long long A23 = f2_pack(a4.z, a4.w);
        const float cj[4] = {c4.x, c4.y, c4.z, c4.w};
        #pragma unroll
        for (int jr = 0; jr < 4; jr++) {
            unsigned long long cd = f2_pack(cj[jr], cj[jr]);
            unsigned long long t0 = f2_relu(f2_add(A01, cd));
            unsigned long long t1 = f2_relu(f2_add(A23, cd));
            acc[jr * 2 + 0] = f2_fma(t0, w2, acc[jr * 2 + 0]);
            acc[jr * 2 + 1] = f2_fma(t1, w2, acc[jr * 2 + 1]);
        }
    }

    // --- all groups publish partials (conflict-free: t64 fastest) ---
    #pragma unroll
    for (int q = 0; q < 8; q++)
        redS[q * 256 + kg * 64 + t64] = acc[q];
    __syncthreads();

    // --- distributed finalize: group kg handles acc slots {2kg, 2kg+1},
    //     i.e. jr = kg, both i-halves.  All 8 warps share the epilogue. ---
    {
        const int jr = kg;
        unsigned long long s0, s1;
        {
            const unsigned long long* r0 = redS + (jr * 2 + 0) * 256 + t64;
            const unsigned long long* r1 = redS + (jr * 2 + 1) * 256 + t64;
            s0 = f2_add(f2_add(r0[0], r0[64]), f2_add(r0[128], r0[192]));
            s1 = f2_add(f2_add(r1[0], r1[64]), f2_add(r1[128], r1[192]));
        }
        const float bias3 = b3[0];
        float* outb = out + (size_t)b * NPAIRS;
        int j = j0 + tj * 4 + jr;
        float v[4];
        f2_unpack(s0, v[0], v[1]);
        f2_unpack(s1, v[2], v[3]);
        #pragma unroll
        for (int pi = 0; pi < 4; pi++) {
            int i = i0 + ti * 4 + pi;
            if (j > i) {
                int rb = i * (NPTS - 1) - ((i * (i - 1)) >> 1) - i - 1;
                float s = bias3 + v[pi];
                outb[rb + j] = __fdividef(1.f, 1.f + __expf(-s));
            }
        }
    }
}

// ---------------------------------------------------------------------------
extern "C" void kernel_launch(void* const* d_in, const int* in_sizes, int n_in,
                              void* d_out, int out_size)
{
    const float* x   = (const float*)d_in[0];
    // d_in[1] = in_hitnr (unused by the reference)
    const float* W1  = (const float*)d_in[2];
    const float* b1  = (const float*)d_in[3];
    const float* W2  = (const float*)d_in[4];
    const float* b2  = (const float*)d_in[5];
    const float* W3  = (const float*)d_in[6];
    const float* b3  = (const float*)d_in[7];
    float* out = (float*)d_out;

    fold_kernel<<<HID, 32>>>(W1, b1, W2, b2);
    pair_kernel<<<dim3(10, BATCH), 256>>>(x, W3, b3, out);
}